// round 5
// baseline (speedup 1.0000x reference)
#include <cuda_runtime.h>
#include <math.h>

#define BB 8
#define NN 4096
#define CC 64
#define NPOINT 1024
#define KK 32
#define MM (BB*NPOINT)      /* 8192  */
#define RR (MM*KK)          /* 262144 */
#define EPSBN 1e-5f
#define SLOPE 0.1f

// ---------------- static device scratch (no allocations) ----------------
__device__ float g_buf[4][RR*CC];      // 0:y_t 1:y1/y3 2:y2 3:y4  (4 x 64MB)
__device__ int   g_fps[MM];
__device__ int   g_knn[RR];
__device__ float g_pn[BB*NN];
__device__ float g_part[4096][2][CC];  // per-conv-block partial sum/sumsq
__device__ float g_aff[5][2][CC];      // per-stage BN affine a,d

__device__ __forceinline__ float leaky(float x){ return x >= 0.f ? x : SLOPE*x; }

// ---------------- per-point squared norms (ref order: (x*x+y*y)+z*z) ----
__global__ void pnorm_kernel(const float* __restrict__ xyz){
    int i = blockIdx.x*blockDim.x + threadIdx.x;
    if (i < BB*NN){
        float x = xyz[3*i], y = xyz[3*i+1], z = xyz[3*i+2];
        g_pn[i] = __fadd_rn(__fadd_rn(__fmul_rn(x,x), __fmul_rn(y,y)), __fmul_rn(z,z));
    }
}

// ---------------- FPS: 1 block/batch, 1024 thr, 4 pts/thr ---------------
// Exact reference semantics: idx[0]=0, 1023 update+first-argmax steps.
// Also writes new_xyz^T into out[0 .. 3*B*NPOINT).
__global__ void __launch_bounds__(1024)
fps_kernel(const float* __restrict__ xyz, float* __restrict__ out){
    __shared__ int s_maxbits, s_idx;
    int b = blockIdx.x, tid = threadIdx.x;
    const float* g = xyz + b*NN*3;

    float px[4], py[4], pz[4], pd[4];
#pragma unroll
    for (int i=0;i<4;++i){
        int j = tid + 1024*i;
        px[i]=g[3*j]; py[i]=g[3*j+1]; pz[i]=g[3*j+2];
        pd[i]=1e10f;
    }
    if (tid==0){
        s_maxbits = 0; s_idx = 0x7fffffff;
        g_fps[b*NPOINT] = 0;
        out[b*3*NPOINT + 0*NPOINT] = g[0];
        out[b*3*NPOINT + 1*NPOINT] = g[1];
        out[b*3*NPOINT + 2*NPOINT] = g[2];
    }
    __syncthreads();

    int far = 0;
    for (int t=1; t<NPOINT; ++t){
        float cx = g[3*far], cy = g[3*far+1], cz = g[3*far+2];
        float bv = 0.f;
#pragma unroll
        for (int i=0;i<4;++i){
            float dx = __fsub_rn(px[i],cx);
            float dy = __fsub_rn(py[i],cy);
            float dz = __fsub_rn(pz[i],cz);
            float d  = __fadd_rn(__fadd_rn(__fmul_rn(dx,dx),__fmul_rn(dy,dy)),
                                 __fmul_rn(dz,dz));
            pd[i] = fminf(pd[i], d);
            bv    = fmaxf(bv, pd[i]);
        }
#pragma unroll
        for (int off=16; off; off>>=1)
            bv = fmaxf(bv, __shfl_xor_sync(0xffffffffu, bv, off));
        if ((tid&31)==0) atomicMax(&s_maxbits, __float_as_int(bv));
        __syncthreads();
        float gm = __int_as_float(s_maxbits);
#pragma unroll
        for (int i=0;i<4;++i)
            if (pd[i] == gm) atomicMin(&s_idx, tid + 1024*i);
        __syncthreads();
        far = s_idx;
        if (tid==0){
            g_fps[b*NPOINT + t] = far;
            out[b*3*NPOINT + 0*NPOINT + t] = g[3*far];
            out[b*3*NPOINT + 1*NPOINT + t] = g[3*far+1];
            out[b*3*NPOINT + 2*NPOINT + t] = g[3*far+2];
            s_maxbits = 0; s_idx = 0x7fffffff;
        }
        __syncthreads();
    }
}

// ---------------- kNN: one warp per query, streaming top-32 -------------
__device__ __forceinline__ void warp_argmax(float& mv, int& ml){
#pragma unroll
    for (int off=16; off; off>>=1){
        float ov = __shfl_xor_sync(0xffffffffu, mv, off);
        int   ol = __shfl_xor_sync(0xffffffffu, ml, off);
        if (ov > mv || (ov == mv && ol < ml)){ mv = ov; ml = ol; }
    }
}

__global__ void __launch_bounds__(256)
knn_kernel(const float* __restrict__ xyz){
    int wid  = threadIdx.x >> 5, lane = threadIdx.x & 31;
    int b = blockIdx.x >> 7;
    int s = ((blockIdx.x & 127) << 3) + wid;

    const float* xb  = xyz + b*NN*3;
    const float* pnb = g_pn + b*NN;

    int qidx = g_fps[b*NPOINT + s];
    float qx = xb[3*qidx], qy = xb[3*qidx+1], qz = xb[3*qidx+2];
    float qn = pnb[qidx];

    float v; int vi;
    {
        int j = lane;
        float dot = __fadd_rn(__fadd_rn(__fmul_rn(qx,xb[3*j]), __fmul_rn(qy,xb[3*j+1])),
                              __fmul_rn(qz,xb[3*j+2]));
        v  = __fadd_rn(__fadd_rn(__fmul_rn(-2.f,dot), qn), pnb[j]);
        vi = j;
    }
    float mv = v; int ml = lane;
    warp_argmax(mv, ml);
    float tau = mv; int maxlane = ml;

    for (int base=32; base<NN; base+=32){
        int j = base + lane;
        float dot = __fadd_rn(__fadd_rn(__fmul_rn(qx,xb[3*j]), __fmul_rn(qy,xb[3*j+1])),
                              __fmul_rn(qz,xb[3*j+2]));
        float cand = __fadd_rn(__fadd_rn(__fmul_rn(-2.f,dot), qn), pnb[j]);

        unsigned mask = __ballot_sync(0xffffffffu, cand < tau);
        while (mask){
            int src  = __ffs(mask) - 1;
            float cv = __shfl_sync(0xffffffffu, cand, src);
            if (lane == maxlane){ v = cv; vi = base + src; }
            if (lane == src) cand = 3.0e38f;
            mv = v; ml = lane;
            warp_argmax(mv, ml);
            tau = mv; maxlane = ml;
            mask = __ballot_sync(0xffffffffu, cand < tau);
        }
    }
    g_knn[(b*NPOINT + s)*KK + lane] = vi;
}

// ---------------- conv: y[r][o] = sum_c x[r][c]*W[o][c] -----------------
// MODE 0: x = gathered features ; MODE 1: x = leaky(affB(in0))
// MODE 2: x = leaky(affB(in0) + leaky(affA(in1)))
// writes raw y to g_buf[oid] and deterministic per-channel partial stats.
template<int MODE>
__global__ void __launch_bounds__(128)
conv_kernel(int i0, int i1, const float* __restrict__ W,
            const float* __restrict__ features, int oid, int affA, int affB){
    __shared__ float As[64*65];
    __shared__ float Wt[64*72];
    __shared__ float sred1[16][CC];
    __shared__ float sred2[16][CC];

    const int tid = threadIdx.x;
    const int rbase = blockIdx.x * 64;

    for (int i = tid; i < 4096; i += 128){
        int o = i >> 6, c = i & 63;
        Wt[c*72 + o] = W[i];
    }
    for (int i = tid; i < 4096; i += 128){
        int row = i >> 6, c = i & 63;
        int r = rbase + row;
        float vv;
        if (MODE == 0){
            int idx = g_knn[r];
            int b   = r >> 15;
            vv = features[((b<<12)+idx)*CC + c];
        } else {
            float x0 = g_buf[i0][r*CC + c];
            float a1 = g_aff[affB][0][c], d1 = g_aff[affB][1][c];
            if (MODE == 1){
                vv = leaky(fmaf(a1, x0, d1));
            } else {
                float x1 = g_buf[i1][r*CC + c];
                float a0 = g_aff[affA][0][c], d0 = g_aff[affA][1][c];
                vv = leaky(fmaf(a1, x0, d1) + leaky(fmaf(a0, x1, d0)));
            }
        }
        As[row*65 + c] = vv;
    }
    __syncthreads();

    const int ry = tid >> 3, ox = tid & 7;
    const int r0 = ry*4, o0 = ox*8;

    float acc[4][8];
#pragma unroll
    for (int j=0;j<4;++j)
#pragma unroll
        for (int o=0;o<8;++o) acc[j][o] = 0.f;

#pragma unroll 4
    for (int c=0;c<CC;++c){
        float4 w0 = *(const float4*)&Wt[c*72 + o0];
        float4 w1 = *(const float4*)&Wt[c*72 + o0 + 4];
        float av[4];
#pragma unroll
        for (int j=0;j<4;++j) av[j] = As[(r0+j)*65 + c];
#pragma unroll
        for (int j=0;j<4;++j){
            acc[j][0] = fmaf(av[j], w0.x, acc[j][0]);
            acc[j][1] = fmaf(av[j], w0.y, acc[j][1]);
            acc[j][2] = fmaf(av[j], w0.z, acc[j][2]);
            acc[j][3] = fmaf(av[j], w0.w, acc[j][3]);
            acc[j][4] = fmaf(av[j], w1.x, acc[j][4]);
            acc[j][5] = fmaf(av[j], w1.y, acc[j][5]);
            acc[j][6] = fmaf(av[j], w1.z, acc[j][6]);
            acc[j][7] = fmaf(av[j], w1.w, acc[j][7]);
        }
    }

    float* out = g_buf[oid];
#pragma unroll
    for (int j=0;j<4;++j){
        int r = rbase + r0 + j;
        *(float4*)&out[r*CC + o0]     = make_float4(acc[j][0],acc[j][1],acc[j][2],acc[j][3]);
        *(float4*)&out[r*CC + o0 + 4] = make_float4(acc[j][4],acc[j][5],acc[j][6],acc[j][7]);
    }
#pragma unroll
    for (int o=0;o<8;++o){
        float s1 = acc[0][o]+acc[1][o]+acc[2][o]+acc[3][o];
        float s2 = acc[0][o]*acc[0][o]+acc[1][o]*acc[1][o]
                 + acc[2][o]*acc[2][o]+acc[3][o]*acc[3][o];
        sred1[ry][o0+o] = s1;
        sred2[ry][o0+o] = s2;
    }
    __syncthreads();
    if (tid < CC){
        float s1=0.f, s2=0.f;
#pragma unroll
        for (int j=0;j<16;++j){ s1 += sred1[j][tid]; s2 += sred2[j][tid]; }
        g_part[blockIdx.x][0][tid] = s1;
        g_part[blockIdx.x][1][tid] = s2;
    }
}

// ---------------- BN affine finalize: 64 blocks (one per channel) -------
__global__ void __launch_bounds__(256)
affine_kernel(int stage, const float* __restrict__ gam, const float* __restrict__ bet){
    __shared__ float r1[256], r2[256];
    int c = blockIdx.x, t = threadIdx.x;
    float s1=0.f, s2=0.f;
    for (int p=t; p<4096; p+=256){ s1 += g_part[p][0][c]; s2 += g_part[p][1][c]; }
    r1[t]=s1; r2[t]=s2; __syncthreads();
    for (int off=128; off; off>>=1){
        if (t < off){ r1[t]+=r1[t+off]; r2[t]+=r2[t+off]; }
        __syncthreads();
    }
    if (t==0){
        float inv  = 1.f/(float)RR;
        float mean = r1[0]*inv;
        float var  = r2[0]*inv - mean*mean;
        float a    = gam[c]/sqrtf(var + EPSBN);
        g_aff[stage][0][c] = a;
        g_aff[stage][1][c] = bet[c] - a*mean;
    }
}

// ---------------- final: recompute x1 and max over K --------------------
__global__ void __launch_bounds__(256)
final_kernel(float* __restrict__ out){
    int tid = threadIdx.x;
    int mi = tid >> 6, c = tid & 63;
    int m = blockIdx.x*4 + mi;
    float a0=g_aff[0][0][c], d0=g_aff[0][1][c];
    float a2=g_aff[2][0][c], d2=g_aff[2][1][c];
    float a4=g_aff[4][0][c], d4=g_aff[4][1][c];
    const float* yt = g_buf[0];
    const float* y2 = g_buf[2];
    const float* y4 = g_buf[3];
    float vmax = -3.4e38f;
    int rb = m*KK;
#pragma unroll 4
    for (int k=0;k<KK;++k){
        int idx = (rb+k)*CC + c;
        float xt = leaky(fmaf(a0, yt[idx], d0));
        float x0 = leaky(fmaf(a2, y2[idx], d2) + xt);
        float x1 = leaky(fmaf(a4, y4[idx], d4) + x0);
        vmax = fmaxf(vmax, x1);
    }
    int b = m >> 10, s = m & 1023;
    out[BB*3*NPOINT + (b*CC + c)*NPOINT + s] = vmax;
}

// ---------------- launch ------------------------------------------------
extern "C" void kernel_launch(void* const* d_in, const int* in_sizes, int n_in,
                              void* d_out, int out_size){
    (void)n_in; (void)out_size;
    const float* xyz  = (const float*)d_in[0];
    const float* feat = (const float*)d_in[1];
    const float *w[5], *gam[5], *bet[5];
    if (in_sizes[3] == CC*CC){
        // setup_inputs dict order: w_t,w1_0,w2_0,w1_1,w2_1 | b* | g* | beta*
        const int wi[5]={2,3,4,5,6}, gi[5]={12,13,14,15,16}, bi[5]={17,18,19,20,21};
        for (int i=0;i<5;++i){ w[i]=(const float*)d_in[wi[i]];
                               gam[i]=(const float*)d_in[gi[i]];
                               bet[i]=(const float*)d_in[bi[i]]; }
    } else {
        // reference signature order: (w,b,g,beta) per stage
        const int wi[5]={2,6,10,14,18}, gi[5]={4,8,12,16,20}, bi[5]={5,9,13,17,21};
        for (int i=0;i<5;++i){ w[i]=(const float*)d_in[wi[i]];
                               gam[i]=(const float*)d_in[gi[i]];
                               bet[i]=(const float*)d_in[bi[i]]; }
    }
    float* out = (float*)d_out;

    pnorm_kernel<<<128,256>>>(xyz);
    fps_kernel<<<BB,1024>>>(xyz, out);
    knn_kernel<<<1024,256>>>(xyz);

    // stage 0: gather+conv w_t -> buf0 (y_t)
    conv_kernel<0><<<4096,128>>>(0,0,w[0],feat,0,0,0);
    affine_kernel<<<64,256>>>(0, gam[0], bet[0]);
    // stage 1: x_t=leaky(aff0(y_t)); conv w1_0 -> buf1 (y1)
    conv_kernel<1><<<4096,128>>>(0,0,w[1],feat,1,0,0);
    affine_kernel<<<64,256>>>(1, gam[1], bet[1]);
    // stage 2: h1=leaky(aff1(y1)); conv w2_0 -> buf2 (y2)
    conv_kernel<1><<<4096,128>>>(1,0,w[2],feat,2,0,1);
    affine_kernel<<<64,256>>>(2, gam[2], bet[2]);
    // stage 3: x0=leaky(aff2(y2)+leaky(aff0(y_t))); conv w1_1 -> buf1 (y3)
    conv_kernel<2><<<4096,128>>>(2,0,w[3],feat,1,0,2);
    affine_kernel<<<64,256>>>(3, gam[3], bet[3]);
    // stage 4: h3=leaky(aff3(y3)); conv w2_1 -> buf3 (y4)
    conv_kernel<1><<<4096,128>>>(1,0,w[4],feat,3,0,3);
    affine_kernel<<<64,256>>>(4, gam[4], bet[4]);

    final_kernel<<<2048,256>>>(out);
}

// round 7
// speedup vs baseline: 1.2980x; 1.2980x over previous
#include <cuda_runtime.h>
#include <math.h>

#define BB 8
#define NN 4096
#define CC 64
#define NPOINT 1024
#define KK 32
#define MM (BB*NPOINT)      /* 8192  */
#define RR (MM*KK)          /* 262144 */
#define EPSBN 1e-5f
#define SLOPE 0.1f

// ---------------- static device scratch (no allocations) ----------------
__device__ float g_buf[4][RR*CC];      // 0:y_t 1:y1/y3 2:y2 3:y4
__device__ int   g_fps[MM];
__device__ int   g_knn[RR];
__device__ float g_pn[BB*NN];
__device__ float g_part[2048][2][CC];  // per-conv-block partial sum/sumsq
__device__ float g_aff[5][2][CC];      // per-stage BN affine a,d

__device__ __forceinline__ float leaky(float x){ return x >= 0.f ? x : SLOPE*x; }

// ---------------- per-point squared norms (ref order: (x*x+y*y)+z*z) ----
__global__ void pnorm_kernel(const float* __restrict__ xyz){
    int i = blockIdx.x*blockDim.x + threadIdx.x;
    if (i < BB*NN){
        float x = xyz[3*i], y = xyz[3*i+1], z = xyz[3*i+2];
        g_pn[i] = __fadd_rn(__fadd_rn(__fmul_rn(x,x), __fmul_rn(y,y)), __fmul_rn(z,z));
    }
}

// ---------------- FPS: 1 block/batch, 1024 thr, 4 pts/thr ---------------
// Exact reference semantics: idx[0]=0; per step min-update + FIRST-max argmax.
// Argmax via packed (valueBits, ~index) max: values >= 0 so u32 ordering ==
// float ordering; larger ~index == smaller index on ties.
__global__ void __launch_bounds__(1024)
fps_kernel(const float* __restrict__ xyz, float* __restrict__ out){
    __shared__ unsigned long long swk[32];
    __shared__ float s_c[3];
    int b = blockIdx.x, tid = threadIdx.x;
    int lane = tid & 31, wid = tid >> 5;
    const float* g = xyz + b*NN*3;

    float px[4], py[4], pz[4], pd[4];
#pragma unroll
    for (int i=0;i<4;++i){
        int j = tid + 1024*i;
        px[i]=g[3*j]; py[i]=g[3*j+1]; pz[i]=g[3*j+2];
        pd[i]=1e10f;
    }
    if (tid == 0){
        g_fps[b*NPOINT] = 0;
        out[b*3*NPOINT + 0*NPOINT] = g[0];
        out[b*3*NPOINT + 1*NPOINT] = g[1];
        out[b*3*NPOINT + 2*NPOINT] = g[2];
        s_c[0]=g[0]; s_c[1]=g[1]; s_c[2]=g[2];
    }
    __syncthreads();

    for (int t=1; t<NPOINT; ++t){
        float cx=s_c[0], cy=s_c[1], cz=s_c[2];
        float bv = -1.f; int bj = 0;
#pragma unroll
        for (int i=0;i<4;++i){
            float dx = __fsub_rn(px[i],cx);
            float dy = __fsub_rn(py[i],cy);
            float dz = __fsub_rn(pz[i],cz);
            float d  = __fadd_rn(__fadd_rn(__fmul_rn(dx,dx),__fmul_rn(dy,dy)),
                                 __fmul_rn(dz,dz));
            float nd = fminf(pd[i], d);
            pd[i] = nd;
            if (nd > bv){ bv = nd; bj = tid + 1024*i; }  // strict > keeps first idx
        }
        // warp argmax: 2x HW redux (values are >= 0 after first point)
        unsigned vb   = (unsigned)__float_as_int(bv);
        unsigned vmax = __reduce_max_sync(0xffffffffu, vb);
        unsigned lo   = (vb == vmax) ? (0xffffffffu - (unsigned)bj) : 0u;
        unsigned lmax = __reduce_max_sync(0xffffffffu, lo);
        if (lane == 0)
            swk[wid] = ((unsigned long long)vmax << 32) | lmax;
        __syncthreads();
        if (wid == 0){
            unsigned long long k = swk[lane];
            unsigned hi  = (unsigned)(k >> 32);
            unsigned hm  = __reduce_max_sync(0xffffffffu, hi);
            unsigned lo2 = (hi == hm) ? (unsigned)k : 0u;
            unsigned lm  = __reduce_max_sync(0xffffffffu, lo2);
            if (lane == 0){
                int far = (int)(0xffffffffu - lm);
                float fx = g[3*far], fy = g[3*far+1], fz = g[3*far+2];
                s_c[0]=fx; s_c[1]=fy; s_c[2]=fz;
                g_fps[b*NPOINT + t] = far;
                out[b*3*NPOINT + 0*NPOINT + t] = fx;
                out[b*3*NPOINT + 1*NPOINT + t] = fy;
                out[b*3*NPOINT + 2*NPOINT + t] = fz;
            }
        }
        __syncthreads();
    }
}

// ---------------- kNN: one warp per query, streaming top-32 -------------
__device__ __forceinline__ void warp_argmax(float& mv, int& ml){
#pragma unroll
    for (int off=16; off; off>>=1){
        float ov = __shfl_xor_sync(0xffffffffu, mv, off);
        int   ol = __shfl_xor_sync(0xffffffffu, ml, off);
        if (ov > mv || (ov == mv && ol < ml)){ mv = ov; ml = ol; }
    }
}

__global__ void __launch_bounds__(256)
knn_kernel(const float* __restrict__ xyz){
    int wid  = threadIdx.x >> 5, lane = threadIdx.x & 31;
    int b = blockIdx.x >> 7;
    int s = ((blockIdx.x & 127) << 3) + wid;

    const float* xb  = xyz + b*NN*3;
    const float* pnb = g_pn + b*NN;

    int qidx = g_fps[b*NPOINT + s];
    float qx = xb[3*qidx], qy = xb[3*qidx+1], qz = xb[3*qidx+2];
    float qn = pnb[qidx];

    float v; int vi;
    {
        int j = lane;
        float dot = __fadd_rn(__fadd_rn(__fmul_rn(qx,xb[3*j]), __fmul_rn(qy,xb[3*j+1])),
                              __fmul_rn(qz,xb[3*j+2]));
        v  = __fadd_rn(__fadd_rn(__fmul_rn(-2.f,dot), qn), pnb[j]);
        vi = j;
    }
    float mv = v; int ml = lane;
    warp_argmax(mv, ml);
    float tau = mv; int maxlane = ml;

    for (int base=32; base<NN; base+=32){
        int j = base + lane;
        float dot = __fadd_rn(__fadd_rn(__fmul_rn(qx,xb[3*j]), __fmul_rn(qy,xb[3*j+1])),
                              __fmul_rn(qz,xb[3*j+2]));
        float cand = __fadd_rn(__fadd_rn(__fmul_rn(-2.f,dot), qn), pnb[j]);

        unsigned mask = __ballot_sync(0xffffffffu, cand < tau);
        while (mask){
            int src  = __ffs(mask) - 1;
            float cv = __shfl_sync(0xffffffffu, cand, src);
            if (lane == maxlane){ v = cv; vi = base + src; }
            if (lane == src) cand = 3.0e38f;
            mv = v; ml = lane;
            warp_argmax(mv, ml);
            tau = mv; maxlane = ml;
            mask = __ballot_sync(0xffffffffu, cand < tau);
        }
    }
    g_knn[(b*NPOINT + s)*KK + lane] = vi;
}

// ---------------- conv: y[r][o] = sum_c x[r][c]*W[o][c] -----------------
// Tile 128 rows x 64 outs, 128 threads, 8x8 per thread. Dynamic smem:
// Wt [64][72] then As [128][65]; stats arrays overlay Wt region afterwards.
#define CONV_SMEM ((64*72 + 128*65)*4)

template<int MODE>
__global__ void __launch_bounds__(128)
conv_kernel(int i0, int i1, const float* __restrict__ W,
            const float* __restrict__ features, int oid, int affA, int affB){
    extern __shared__ float sm[];
    float* Wt = sm;            // [64][72]
    float* As = sm + 64*72;    // [128][65]

    const int tid = threadIdx.x;
    const int rbase = blockIdx.x * 128;

    for (int i = tid; i < 4096; i += 128){
        int o = i >> 6, c = i & 63;
        Wt[c*72 + o] = W[i];
    }
    for (int i = tid; i < 8192; i += 128){
        int row = i >> 6, c = i & 63;
        int r = rbase + row;
        float vv;
        if (MODE == 0){
            int idx = g_knn[r];
            int b   = r >> 15;
            vv = features[((b<<12)+idx)*CC + c];
        } else {
            float x0 = g_buf[i0][r*CC + c];
            float a1 = g_aff[affB][0][c], d1 = g_aff[affB][1][c];
            if (MODE == 1){
                vv = leaky(fmaf(a1, x0, d1));
            } else {
                float x1 = g_buf[i1][r*CC + c];
                float a0 = g_aff[affA][0][c], d0 = g_aff[affA][1][c];
                vv = leaky(fmaf(a1, x0, d1) + leaky(fmaf(a0, x1, d0)));
            }
        }
        As[row*65 + c] = vv;
    }
    __syncthreads();

    const int ry = tid >> 3, ox = tid & 7;
    const int r0 = ry*8, o0 = ox*8;

    float acc[8][8];
#pragma unroll
    for (int j=0;j<8;++j)
#pragma unroll
        for (int o=0;o<8;++o) acc[j][o] = 0.f;

#pragma unroll 2
    for (int c=0;c<CC;++c){
        float4 w0 = *(const float4*)&Wt[c*72 + o0];
        float4 w1 = *(const float4*)&Wt[c*72 + o0 + 4];
        float av[8];
#pragma unroll
        for (int j=0;j<8;++j) av[j] = As[(r0+j)*65 + c];
#pragma unroll
        for (int j=0;j<8;++j){
            acc[j][0] = fmaf(av[j], w0.x, acc[j][0]);
            acc[j][1] = fmaf(av[j], w0.y, acc[j][1]);
            acc[j][2] = fmaf(av[j], w0.z, acc[j][2]);
            acc[j][3] = fmaf(av[j], w0.w, acc[j][3]);
            acc[j][4] = fmaf(av[j], w1.x, acc[j][4]);
            acc[j][5] = fmaf(av[j], w1.y, acc[j][5]);
            acc[j][6] = fmaf(av[j], w1.z, acc[j][6]);
            acc[j][7] = fmaf(av[j], w1.w, acc[j][7]);
        }
    }

    float* outb = g_buf[oid];
#pragma unroll
    for (int j=0;j<8;++j){
        int r = rbase + r0 + j;
        *(float4*)&outb[r*CC + o0]     = make_float4(acc[j][0],acc[j][1],acc[j][2],acc[j][3]);
        *(float4*)&outb[r*CC + o0 + 4] = make_float4(acc[j][4],acc[j][5],acc[j][6],acc[j][7]);
    }

    // stats: overlay reduction arrays onto the Wt region (done with smem reads)
    __syncthreads();
    float* sred1 = sm;           // [16][64]
    float* sred2 = sm + 1024;    // [16][64]
#pragma unroll
    for (int o=0;o<8;++o){
        float s1 = 0.f, s2 = 0.f;
#pragma unroll
        for (int j=0;j<8;++j){ s1 += acc[j][o]; s2 += acc[j][o]*acc[j][o]; }
        sred1[ry*64 + o0 + o] = s1;
        sred2[ry*64 + o0 + o] = s2;
    }
    __syncthreads();
    if (tid < CC){
        float s1=0.f, s2=0.f;
#pragma unroll
        for (int j=0;j<16;++j){ s1 += sred1[j*64 + tid]; s2 += sred2[j*64 + tid]; }
        g_part[blockIdx.x][0][tid] = s1;
        g_part[blockIdx.x][1][tid] = s2;
    }
}

// ---------------- BN affine finalize: 64 blocks (one per channel) -------
__global__ void __launch_bounds__(256)
affine_kernel(int stage, const float* __restrict__ gam, const float* __restrict__ bet){
    __shared__ float r1[256], r2[256];
    int c = blockIdx.x, t = threadIdx.x;
    float s1=0.f, s2=0.f;
    for (int p=t; p<2048; p+=256){ s1 += g_part[p][0][c]; s2 += g_part[p][1][c]; }
    r1[t]=s1; r2[t]=s2; __syncthreads();
    for (int off=128; off; off>>=1){
        if (t < off){ r1[t]+=r1[t+off]; r2[t]+=r2[t+off]; }
        __syncthreads();
    }
    if (t==0){
        float inv  = 1.f/(float)RR;
        float mean = r1[0]*inv;
        float var  = r2[0]*inv - mean*mean;
        float a    = gam[c]/sqrtf(var + EPSBN);
        g_aff[stage][0][c] = a;
        g_aff[stage][1][c] = bet[c] - a*mean;
    }
}

// ---------------- final: recompute x1 and max over K --------------------
__global__ void __launch_bounds__(256)
final_kernel(float* __restrict__ out){
    int tid = threadIdx.x;
    int mi = tid >> 6, c = tid & 63;
    int m = blockIdx.x*4 + mi;
    float a0=g_aff[0][0][c], d0=g_aff[0][1][c];
    float a2=g_aff[2][0][c], d2=g_aff[2][1][c];
    float a4=g_aff[4][0][c], d4=g_aff[4][1][c];
    const float* yt = g_buf[0];
    const float* y2 = g_buf[2];
    const float* y4 = g_buf[3];
    float vmax = -3.4e38f;
    int rb = m*KK;
#pragma unroll 4
    for (int k=0;k<KK;++k){
        int idx = (rb+k)*CC + c;
        float xt = leaky(fmaf(a0, yt[idx], d0));
        float x0 = leaky(fmaf(a2, y2[idx], d2) + xt);
        float x1 = leaky(fmaf(a4, y4[idx], d4) + x0);
        vmax = fmaxf(vmax, x1);
    }
    int b = m >> 10, s = m & 1023;
    out[BB*3*NPOINT + (b*CC + c)*NPOINT + s] = vmax;
}

// ---------------- launch ------------------------------------------------
extern "C" void kernel_launch(void* const* d_in, const int* in_sizes, int n_in,
                              void* d_out, int out_size){
    (void)n_in; (void)out_size;
    const float* xyz  = (const float*)d_in[0];
    const float* feat = (const float*)d_in[1];
    const float *w[5], *gam[5], *bet[5];
    if (in_sizes[3] == CC*CC){
        const int wi[5]={2,3,4,5,6}, gi[5]={12,13,14,15,16}, bi[5]={17,18,19,20,21};
        for (int i=0;i<5;++i){ w[i]=(const float*)d_in[wi[i]];
                               gam[i]=(const float*)d_in[gi[i]];
                               bet[i]=(const float*)d_in[bi[i]]; }
    } else {
        const int wi[5]={2,6,10,14,18}, gi[5]={4,8,12,16,20}, bi[5]={5,9,13,17,21};
        for (int i=0;i<5;++i){ w[i]=(const float*)d_in[wi[i]];
                               gam[i]=(const float*)d_in[gi[i]];
                               bet[i]=(const float*)d_in[bi[i]]; }
    }
    float* out = (float*)d_out;

    cudaFuncSetAttribute(conv_kernel<0>, cudaFuncAttributeMaxDynamicSharedMemorySize, CONV_SMEM);
    cudaFuncSetAttribute(conv_kernel<1>, cudaFuncAttributeMaxDynamicSharedMemorySize, CONV_SMEM);
    cudaFuncSetAttribute(conv_kernel<2>, cudaFuncAttributeMaxDynamicSharedMemorySize, CONV_SMEM);

    pnorm_kernel<<<128,256>>>(xyz);
    fps_kernel<<<BB,1024>>>(xyz, out);
    knn_kernel<<<1024,256>>>(xyz);

    conv_kernel<0><<<2048,128,CONV_SMEM>>>(0,0,w[0],feat,0,0,0);
    affine_kernel<<<64,256>>>(0, gam[0], bet[0]);
    conv_kernel<1><<<2048,128,CONV_SMEM>>>(0,0,w[1],feat,1,0,0);
    affine_kernel<<<64,256>>>(1, gam[1], bet[1]);
    conv_kernel<1><<<2048,128,CONV_SMEM>>>(1,0,w[2],feat,2,0,1);
    affine_kernel<<<64,256>>>(2, gam[2], bet[2]);
    conv_kernel<2><<<2048,128,CONV_SMEM>>>(2,0,w[3],feat,1,0,2);
    affine_kernel<<<64,256>>>(3, gam[3], bet[3]);
    conv_kernel<1><<<2048,128,CONV_SMEM>>>(1,0,w[4],feat,3,0,3);
    affine_kernel<<<64,256>>>(4, gam[4], bet[4]);

    final_kernel<<<2048,256>>>(out);
}

// round 9
// speedup vs baseline: 1.4016x; 1.0798x over previous
#include <cuda_runtime.h>
#include <math.h>

#define BB 8
#define NN 4096
#define CC 64
#define NPOINT 1024
#define KK 32
#define MM (BB*NPOINT)
#define RR (MM*KK)
#define EPSBN 1e-5f
#define SLOPE 0.1f

typedef unsigned long long u64;

__device__ float g_buf[4][RR*CC];      // 0:y_t 1:y1/y3 2:y2 3:y4
__device__ int   g_fps[MM];
__device__ int   g_knn[RR];
__device__ float g_pn[BB*NN];
__device__ float g_part[2048][2][CC];
__device__ float g_aff[5][2][CC];

__device__ __forceinline__ float leaky(float x){ return x>=0.f ? x : SLOPE*x; }

// ---- packed f32x2 (bitwise == two scalar rn ops) ----
#define ADD2(o,a,b) asm("add.rn.f32x2 %0,%1,%2;":"=l"(o):"l"(a),"l"(b))
#define MUL2(o,a,b) asm("mul.rn.f32x2 %0,%1,%2;":"=l"(o):"l"(a),"l"(b))
#define PACK2(o,lo,hi) asm("mov.b64 %0,{%1,%2};":"=l"(o):"f"(lo),"f"(hi))
#define UNPK2(lo,hi,i) asm("mov.b64 {%0,%1},%2;":"=f"(lo),"=f"(hi):"l"(i))

// ---------------- per-point squared norms (ref order) ----------------
__global__ void pnorm_kernel(const float* __restrict__ xyz){
    int i = blockIdx.x*blockDim.x + threadIdx.x;
    if (i < BB*NN){
        float x = xyz[3*i], y = xyz[3*i+1], z = xyz[3*i+2];
        g_pn[i] = __fadd_rn(__fadd_rn(__fmul_rn(x,x), __fmul_rn(y,y)), __fmul_rn(z,z));
    }
}

// ---------------- FPS: 1 block/batch, 1024 thr, 4 pts/thr ---------------
// Bit-exact reference semantics. One barrier per step: per-warp argmax keys
// go to a parity-double-buffered smem array; after the single sync ALL warps
// redundantly reduce the 32 keys, so no second barrier / serial section.
__global__ void __launch_bounds__(1024)
fps_kernel(const float* __restrict__ xyz, float* __restrict__ out){
    __shared__ u64 swk[2][32];
    int b=blockIdx.x, tid=threadIdx.x, lane=tid&31, wid=tid>>5;
    const float* g = xyz + b*NN*3;

    u64 px01,px23,py01,py23,pz01,pz23;
    {
        float a0=g[3*tid],        a1=g[3*(tid+1024)];
        float a2=g[3*(tid+2048)], a3=g[3*(tid+3072)];
        PACK2(px01,a0,a1); PACK2(px23,a2,a3);
        float b0=g[3*tid+1],        b1=g[3*(tid+1024)+1];
        float b2=g[3*(tid+2048)+1], b3=g[3*(tid+3072)+1];
        PACK2(py01,b0,b1); PACK2(py23,b2,b3);
        float c0=g[3*tid+2],        c1=g[3*(tid+1024)+2];
        float c2=g[3*(tid+2048)+2], c3=g[3*(tid+3072)+2];
        PACK2(pz01,c0,c1); PACK2(pz23,c2,c3);
    }
    float pd0=1e10f,pd1=1e10f,pd2=1e10f,pd3=1e10f;
    if (tid==0){
        g_fps[b*NPOINT] = 0;
        out[b*3*NPOINT + 0*NPOINT] = g[0];
        out[b*3*NPOINT + 1*NPOINT] = g[1];
        out[b*3*NPOINT + 2*NPOINT] = g[2];
    }
    float cx=g[0], cy=g[1], cz=g[2];

    for (int t=1; t<NPOINT; ++t){
        // ---- phase A: min-update + per-warp argmax ----
        float nx=__int_as_float(__float_as_int(cx)^0x80000000);
        float ny=__int_as_float(__float_as_int(cy)^0x80000000);
        float nz=__int_as_float(__float_as_int(cz)^0x80000000);
        u64 ncx,ncy,ncz; PACK2(ncx,nx,nx); PACK2(ncy,ny,ny); PACK2(ncz,nz,nz);
        u64 dx01,dx23,dy01,dy23,dz01,dz23,t01,t23,d01v,d23v;
        ADD2(dx01,px01,ncx); ADD2(dx23,px23,ncx);
        ADD2(dy01,py01,ncy); ADD2(dy23,py23,ncy);
        ADD2(dz01,pz01,ncz); ADD2(dz23,pz23,ncz);
        MUL2(dx01,dx01,dx01); MUL2(dx23,dx23,dx23);
        MUL2(dy01,dy01,dy01); MUL2(dy23,dy23,dy23);
        MUL2(dz01,dz01,dz01); MUL2(dz23,dz23,dz23);
        ADD2(t01,dx01,dy01);  ADD2(t23,dx23,dy23);
        ADD2(d01v,t01,dz01);  ADD2(d23v,t23,dz23);
        float d0,d1,d2,d3; UNPK2(d0,d1,d01v); UNPK2(d2,d3,d23v);
        pd0=fminf(pd0,d0); pd1=fminf(pd1,d1); pd2=fminf(pd2,d2); pd3=fminf(pd3,d3);
        float bv = fmaxf(fmaxf(pd0,pd1), fmaxf(pd2,pd3));

        unsigned vb   = (unsigned)__float_as_int(bv);          // pd>=0: u32 order==f32 order
        unsigned vmax = __reduce_max_sync(0xffffffffu, vb);
        unsigned lo = 0u;
        if (vb == vmax){                                       // lazy first-index recovery
            int bj = (pd0==bv) ? tid : (pd1==bv) ? tid+1024 : (pd2==bv) ? tid+2048 : tid+3072;
            lo = ~(unsigned)bj;                                // bigger == smaller index
        }
        unsigned lmax = __reduce_max_sync(0xffffffffu, lo);
        if (lane==0) swk[t&1][wid] = ((u64)vmax<<32) | lmax;
        __syncthreads();

        // ---- phase B: all warps redundantly reduce the 32 keys ----
        u64 k = swk[t&1][lane];
        unsigned hi  = (unsigned)(k>>32);
        unsigned hm  = __reduce_max_sync(0xffffffffu, hi);
        unsigned lo2 = (hi==hm) ? (unsigned)k : 0u;
        unsigned lm  = __reduce_max_sync(0xffffffffu, lo2);
        int far = (int)(~lm);
        cx = __ldg(&g[3*far]); cy = __ldg(&g[3*far+1]); cz = __ldg(&g[3*far+2]);
        if (tid==0){
            g_fps[b*NPOINT + t] = far;
            out[b*3*NPOINT + 0*NPOINT + t] = cx;
            out[b*3*NPOINT + 1*NPOINT + t] = cy;
            out[b*3*NPOINT + 2*NPOINT + t] = cz;
        }
        // no second barrier: next step writes swk[(t+1)&1] (other buffer)
    }
}

// ---------------- kNN: one warp per query, streaming top-32 -------------
__device__ __forceinline__ void warp_argmax(float& mv, int& ml){
#pragma unroll
    for (int off=16; off; off>>=1){
        float ov = __shfl_xor_sync(0xffffffffu, mv, off);
        int   ol = __shfl_xor_sync(0xffffffffu, ml, off);
        if (ov > mv || (ov == mv && ol < ml)){ mv = ov; ml = ol; }
    }
}

__global__ void __launch_bounds__(256)
knn_kernel(const float* __restrict__ xyz){
    int wid  = threadIdx.x >> 5, lane = threadIdx.x & 31;
    int b = blockIdx.x >> 7;
    int s = ((blockIdx.x & 127) << 3) + wid;
    const float* xb  = xyz + b*NN*3;
    const float* pnb = g_pn + b*NN;

    int qidx = g_fps[b*NPOINT + s];
    float qx = xb[3*qidx], qy = xb[3*qidx+1], qz = xb[3*qidx+2];
    float qn = pnb[qidx];

    float v; int vi;
    {
        int j = lane;
        float dot = __fadd_rn(__fadd_rn(__fmul_rn(qx,xb[3*j]), __fmul_rn(qy,xb[3*j+1])),
                              __fmul_rn(qz,xb[3*j+2]));
        v  = __fadd_rn(__fadd_rn(__fmul_rn(-2.f,dot), qn), pnb[j]);
        vi = j;
    }
    float mv = v; int ml = lane;
    warp_argmax(mv, ml);
    float tau = mv; int maxlane = ml;

    for (int base=32; base<NN; base+=32){
        int j = base + lane;
        float dot = __fadd_rn(__fadd_rn(__fmul_rn(qx,xb[3*j]), __fmul_rn(qy,xb[3*j+1])),
                              __fmul_rn(qz,xb[3*j+2]));
        float cand = __fadd_rn(__fadd_rn(__fmul_rn(-2.f,dot), qn), pnb[j]);
        unsigned mask = __ballot_sync(0xffffffffu, cand < tau);
        while (mask){
            int src  = __ffs(mask) - 1;
            float cv = __shfl_sync(0xffffffffu, cand, src);
            if (lane == maxlane){ v = cv; vi = base + src; }
            if (lane == src) cand = 3.0e38f;
            mv = v; ml = lane;
            warp_argmax(mv, ml);
            tau = mv; maxlane = ml;
            mask = __ballot_sync(0xffffffffu, cand < tau);
        }
    }
    g_knn[(b*NPOINT + s)*KK + lane] = vi;
}

// ---------------- conv (SIMT FFMA, R7-proven): 128x64 tile, 8x8/thr -----
#define CONV_SMEM ((64*72 + 128*65)*4)

template<int MODE>
__global__ void __launch_bounds__(128)
conv_kernel(int i0, int i1, const float* __restrict__ W,
            const float* __restrict__ features, int oid, int affA, int affB){
    extern __shared__ float sm[];
    float* Wt = sm;            // [64][72]
    float* As = sm + 64*72;    // [128][65]

    const int tid = threadIdx.x;
    const int rbase = blockIdx.x * 128;

    for (int i = tid; i < 4096; i += 128){
        int o = i >> 6, c = i & 63;
        Wt[c*72 + o] = W[i];
    }
    for (int i = tid; i < 8192; i += 128){
        int row = i >> 6, c = i & 63;
        int r = rbase + row;
        float vv;
        if (MODE == 0){
            int idx = g_knn[r];
            int bb  = r >> 15;
            vv = features[((bb<<12)+idx)*CC + c];
        } else {
            float x0 = g_buf[i0][(size_t)r*CC + c];
            float a1 = g_aff[affB][0][c], d1 = g_aff[affB][1][c];
            if (MODE == 1){
                vv = leaky(fmaf(a1, x0, d1));
            } else {
                float x1 = g_buf[i1][(size_t)r*CC + c];
                float a0 = g_aff[affA][0][c], d0 = g_aff[affA][1][c];
                vv = leaky(fmaf(a1, x0, d1) + leaky(fmaf(a0, x1, d0)));
            }
        }
        As[row*65 + c] = vv;
    }
    __syncthreads();

    const int ry = tid >> 3, ox = tid & 7;
    const int r0 = ry*8, o0 = ox*8;

    float acc[8][8];
#pragma unroll
    for (int j=0;j<8;++j)
#pragma unroll
        for (int o=0;o<8;++o) acc[j][o] = 0.f;

#pragma unroll 2
    for (int c=0;c<CC;++c){
        float4 w0 = *(const float4*)&Wt[c*72 + o0];
        float4 w1 = *(const float4*)&Wt[c*72 + o0 + 4];
        float av[8];
#pragma unroll
        for (int j=0;j<8;++j) av[j] = As[(r0+j)*65 + c];
#pragma unroll
        for (int j=0;j<8;++j){
            acc[j][0] = fmaf(av[j], w0.x, acc[j][0]);
            acc[j][1] = fmaf(av[j], w0.y, acc[j][1]);
            acc[j][2] = fmaf(av[j], w0.z, acc[j][2]);
            acc[j][3] = fmaf(av[j], w0.w, acc[j][3]);
            acc[j][4] = fmaf(av[j], w1.x, acc[j][4]);
            acc[j][5] = fmaf(av[j], w1.y, acc[j][5]);
            acc[j][6] = fmaf(av[j], w1.z, acc[j][6]);
            acc[j][7] = fmaf(av[j], w1.w, acc[j][7]);
        }
    }

    float* outb = g_buf[oid];
#pragma unroll
    for (int j=0;j<8;++j){
        size_t r = (size_t)(rbase + r0 + j);
        *(float4*)&outb[r*CC + o0]     = make_float4(acc[j][0],acc[j][1],acc[j][2],acc[j][3]);
        *(float4*)&outb[r*CC + o0 + 4] = make_float4(acc[j][4],acc[j][5],acc[j][6],acc[j][7]);
    }

    __syncthreads();
    float* sred1 = sm;           // overlay Wt region: [16][64]
    float* sred2 = sm + 1024;
#pragma unroll
    for (int o=0;o<8;++o){
        float s1 = 0.f, s2 = 0.f;
#pragma unroll
        for (int j=0;j<8;++j){ s1 += acc[j][o]; s2 += acc[j][o]*acc[j][o]; }
        sred1[ry*64 + o0 + o] = s1;
        sred2[ry*64 + o0 + o] = s2;
    }
    __syncthreads();
    if (tid < CC){
        float s1=0.f, s2=0.f;
#pragma unroll
        for (int j=0;j<16;++j){ s1 += sred1[j*64 + tid]; s2 += sred2[j*64 + tid]; }
        g_part[blockIdx.x][0][tid] = s1;
        g_part[blockIdx.x][1][tid] = s2;
    }
}

// ---------------- BN affine finalize ----------------
__global__ void __launch_bounds__(256)
affine_kernel(int stage, const float* __restrict__ gam, const float* __restrict__ bet){
    __shared__ float r1[256], r2[256];
    int c = blockIdx.x, t = threadIdx.x;
    float s1=0.f, s2=0.f;
    for (int p=t; p<2048; p+=256){ s1 += g_part[p][0][c]; s2 += g_part[p][1][c]; }
    r1[t]=s1; r2[t]=s2; __syncthreads();
    for (int off=128; off; off>>=1){
        if (t < off){ r1[t]+=r1[t+off]; r2[t]+=r2[t+off]; }
        __syncthreads();
    }
    if (t==0){
        float inv  = 1.f/(float)RR;
        float mean = r1[0]*inv;
        float var  = r2[0]*inv - mean*mean;
        float a    = gam[c]/sqrtf(var + EPSBN);
        g_aff[stage][0][c] = a;
        g_aff[stage][1][c] = bet[c] - a*mean;
    }
}

// ---------------- final: recompute x1 and max over K ----------------
__global__ void __launch_bounds__(256)
final_kernel(float* __restrict__ out){
    int tid = threadIdx.x;
    int mi = tid >> 6, c = tid & 63;
    int m = blockIdx.x*4 + mi;
    float a0=g_aff[0][0][c], d0=g_aff[0][1][c];
    float a2=g_aff[2][0][c], d2=g_aff[2][1][c];
    float a4=g_aff[4][0][c], d4=g_aff[4][1][c];
    const float* yt = g_buf[0];
    const float* y2 = g_buf[2];
    const float* y4 = g_buf[3];
    float vmax = -3.4e38f;
    int rb = m*KK;
#pragma unroll 4
    for (int k=0;k<KK;++k){
        size_t idx = (size_t)(rb+k)*CC + c;
        float xt = leaky(fmaf(a0, yt[idx], d0));
        float x0 = leaky(fmaf(a2, y2[idx], d2) + xt);
        float x1 = leaky(fmaf(a4, y4[idx], d4) + x0);
        vmax = fmaxf(vmax, x1);
    }
    int b = m >> 10, s = m & 1023;
    out[BB*3*NPOINT + (b*CC + c)*NPOINT + s] = vmax;
}

// ---------------- launch ----------------
extern "C" void kernel_launch(void* const* d_in, const int* in_sizes, int n_in,
                              void* d_out, int out_size){
    (void)n_in; (void)out_size;
    const float* xyz  = (const float*)d_in[0];
    const float* feat = (const float*)d_in[1];
    const float *w[5], *gam[5], *bet[5];
    if (in_sizes[3] == CC*CC){
        const int wi[5]={2,3,4,5,6}, gi[5]={12,13,14,15,16}, bi[5]={17,18,19,20,21};
        for (int i=0;i<5;++i){ w[i]=(const float*)d_in[wi[i]];
                               gam[i]=(const float*)d_in[gi[i]];
                               bet[i]=(const float*)d_in[bi[i]]; }
    } else {
        const int wi[5]={2,6,10,14,18}, gi[5]={4,8,12,16,20}, bi[5]={5,9,13,17,21};
        for (int i=0;i<5;++i){ w[i]=(const float*)d_in[wi[i]];
                               gam[i]=(const float*)d_in[gi[i]];
                               bet[i]=(const float*)d_in[bi[i]]; }
    }
    float* out = (float*)d_out;

    cudaFuncSetAttribute(conv_kernel<0>, cudaFuncAttributeMaxDynamicSharedMemorySize, CONV_SMEM);
    cudaFuncSetAttribute(conv_kernel<1>, cudaFuncAttributeMaxDynamicSharedMemorySize, CONV_SMEM);
    cudaFuncSetAttribute(conv_kernel<2>, cudaFuncAttributeMaxDynamicSharedMemorySize, CONV_SMEM);

    pnorm_kernel<<<128,256>>>(xyz);
    fps_kernel<<<BB,1024>>>(xyz, out);
    knn_kernel<<<1024,256>>>(xyz);

    conv_kernel<0><<<2048,128,CONV_SMEM>>>(0,0,w[0],feat,0,0,0);
    affine_kernel<<<64,256>>>(0, gam[0], bet[0]);
    conv_kernel<1><<<2048,128,CONV_SMEM>>>(0,0,w[1],feat,1,0,0);
    affine_kernel<<<64,256>>>(1, gam[1], bet[1]);
    conv_kernel<1><<<2048,128,CONV_SMEM>>>(1,0,w[2],feat,2,0,1);
    affine_kernel<<<64,256>>>(2, gam[2], bet[2]);
    conv_kernel<2><<<2048,128,CONV_SMEM>>>(2,0,w[3],feat,1,0,2);
    affine_kernel<<<64,256>>>(3, gam[3], bet[3]);
    conv_kernel<1><<<2048,128,CONV_SMEM>>>(1,0,w[4],feat,3,0,3);
    affine_kernel<<<64,256>>>(4, gam[4], bet[4]);

    final_kernel<<<2048,256>>>(out);
}